// round 8
// baseline (speedup 1.0000x reference)
#include <cuda_runtime.h>
#include <cuda_bf16.h>
#include <cstdint>

// ---------------- problem constants ----------------
#define N_ROWS   262144
#define DIMS     64
#define KCODES   1024
#define BM       128
#define THREADS  512
#define GRID     (N_ROWS / BM)              // 2048
#define QOUT     (N_ROWS * DIMS)
#define CAND_CAP 8                          // shared per-row list
#define CAP_T    4                          // per-thread per-row buffer

// ---------------- smem layout (bytes) ----------------
#define SM_A     0                          // 128 rows x 144B bf16 (padded)
#define SM_B     18432                      // 1024 codes x 128B bf16 (XOR-swizzled)
#define SM_CN    149504                     // 1024 fp32
#define SM_BUF   153600                     // 512 thr x 4 rows x 4 x 8B = 65536
#define SM_CA    219136                     // 128 x 8 x 8B
#define SM_RM    227328                     // 128 u32
#define SM_CT    227840                     // 128 int
#define SM_TK    228352                     // 128 int
#define SM_DL    228864                     // 128 fp32
#define SM_XN    229376                     // 128 fp32
#define SM_OV    229888                     // 128 int overflow flags
#define SM_FLAG  230400                     // 4B
#define SMEM_TOTAL 230416

#define A_STRIDE 144

// ---------------- device globals ----------------
__device__ __align__(16) float    g_cnorm[KCODES];
__device__ __align__(16) uint32_t g_cbbf16[KCODES * DIMS / 2];
__device__ unsigned int           g_counts[KCODES];
__device__ float                  g_loss[2];
__device__ int                    g_cmax_bits;
__device__ unsigned int           g_done;

// ---------------- helpers ----------------
static __device__ __forceinline__ unsigned fkey(float f) {
    int b = __float_as_int(f);
    return (unsigned)(b >= 0 ? (b | 0x80000000) : ~b);
}
static __device__ __forceinline__ float finv(unsigned k) {
    int b = (k & 0x80000000u) ? (int)(k & 0x7fffffffu) : ~(int)k;
    return __int_as_float(b);
}
static __device__ __forceinline__ void mma16816(
    float& c0, float& c1, float& c2, float& c3,
    uint32_t a0, uint32_t a1, uint32_t a2, uint32_t a3,
    uint32_t b0, uint32_t b1)
{
    asm volatile(
        "mma.sync.aligned.m16n8k16.row.col.f32.bf16.bf16.f32 "
        "{%0,%1,%2,%3}, {%4,%5,%6,%7}, {%8,%9}, {%0,%1,%2,%3};"
        : "+f"(c0), "+f"(c1), "+f"(c2), "+f"(c3)
        : "r"(a0), "r"(a1), "r"(a2), "r"(a3), "r"(b0), "r"(b1));
}

// ---------------- prep: resets + cnorm + cmax + bf16 codebook ----------------
__global__ void vq_prep(const float* __restrict__ cb) {
    int k = threadIdx.x;   // 1024 threads, 1 block
    g_counts[k] = 0u;
    if (k < 2) g_loss[k] = 0.0f;
    if (k == 2) g_done = 0u;

    const float4* c4 = (const float4*)(cb + (size_t)k * DIMS);
    uint32_t* ob = g_cbbf16 + k * (DIMS / 2);
    float s = 0.0f;
#pragma unroll
    for (int j = 0; j < 16; j++) {
        float4 v = c4[j];
        s += v.x * v.x + v.y * v.y + v.z * v.z + v.w * v.w;
        __nv_bfloat162 p0 = __float22bfloat162_rn(make_float2(v.x, v.y));
        __nv_bfloat162 p1 = __float22bfloat162_rn(make_float2(v.z, v.w));
        ob[j * 2 + 0] = *(uint32_t*)&p0;
        ob[j * 2 + 1] = *(uint32_t*)&p1;
    }
    g_cnorm[k] = 0.5f * s;
    atomicMax(&g_cmax_bits, __float_as_int(sqrtf(s)));
}

// ---------------- main ----------------
extern __shared__ char smem[];

__global__ __launch_bounds__(THREADS, 1)
void vq_main(const float* __restrict__ inp, const float* __restrict__ cb,
             float* __restrict__ out)
{
    const int tid  = threadIdx.x;
    const int w    = tid >> 5;
    const int lane = tid & 31;
    const int row0 = blockIdx.x * BM;

    char*     As = smem + SM_A;
    float*    CN = (float*)(smem + SM_CN);
    float2*   CA = (float2*)(smem + SM_CA);
    unsigned* RM = (unsigned*)(smem + SM_RM);
    int*      CT = (int*)(smem + SM_CT);
    int*      TK = (int*)(smem + SM_TK);
    float*    DL = (float*)(smem + SM_DL);
    float*    XN = (float*)(smem + SM_XN);
    int*      OV = (int*)(smem + SM_OV);
    int*      FLAG = (int*)(smem + SM_FLAG);

    // ---- fills: inits, A bf16 + row norms, B swizzled, cnorm ----
    if (tid < 128) { RM[tid] = 0u; CT[tid] = 0; OV[tid] = 0; }
#pragma unroll
    for (int i = 0; i < 4; i++) {           // A + XN: 2048 float4 chunks
        int idx = tid + i * THREADS;
        int r = idx >> 4, j = idx & 15;
        float4 v = *(const float4*)(inp + (size_t)(row0 + r) * DIMS + j * 4);
        __nv_bfloat162 p0 = __float22bfloat162_rn(make_float2(v.x, v.y));
        __nv_bfloat162 p1 = __float22bfloat162_rn(make_float2(v.z, v.w));
        *(uint2*)(As + r * A_STRIDE + j * 8) = make_uint2(*(uint32_t*)&p0, *(uint32_t*)&p1);
        float s = v.x * v.x + v.y * v.y + v.z * v.z + v.w * v.w;
        s += __shfl_xor_sync(0xffffffffu, s, 8);
        s += __shfl_xor_sync(0xffffffffu, s, 4);
        s += __shfl_xor_sync(0xffffffffu, s, 2);
        s += __shfl_xor_sync(0xffffffffu, s, 1);
        if ((lane & 15) == 0) XN[r] = s;
    }
#pragma unroll
    for (int i = 0; i < 16; i++) {          // B: 8192 16B chunks, XOR-swizzled
        int idx = tid + i * THREADS;
        int c = idx >> 3, u = idx & 7;
        uint4 v = *(const uint4*)(g_cbbf16 + (size_t)idx * 4);
        *(uint4*)(smem + SM_B + c * 128 + ((u ^ (c & 7)) * 16)) = v;
    }
#pragma unroll
    for (int i = 0; i < 2; i++) CN[tid + i * THREADS] = g_cnorm[tid + i * THREADS];
    __syncthreads();

    if (tid < 128)
        DL[tid] = sqrtf(XN[tid]) * __int_as_float(g_cmax_bits) * (2.2f / 256.0f) + 1e-4f;
    __syncthreads();

    // ---- warp work assignment: 32 rows x 256 codes ----
    const int rowblk = (w & 3) * 32;
    const int colq   = (w >> 2) * 256;
    const int ra = rowblk + (lane >> 2);
    const int rb = ra + 8;
    const int rc = ra + 16;
    const int rd = ra + 24;
    const int rows_[4] = { ra, rb, rc, rd };
    float dl[4];
    dl[0] = DL[ra]; dl[1] = DL[rb]; dl[2] = DL[rc]; dl[3] = DL[rd];

    // ---- A fragments: persistent registers ----
    uint32_t af[4][8];
#pragma unroll
    for (int ks = 0; ks < 4; ks++) {
        int kb = ks * 32 + (lane & 3) * 4;
        af[ks][0] = *(const uint32_t*)(As + ra * A_STRIDE + kb);
        af[ks][1] = *(const uint32_t*)(As + rb * A_STRIDE + kb);
        af[ks][2] = *(const uint32_t*)(As + ra * A_STRIDE + kb + 16);
        af[ks][3] = *(const uint32_t*)(As + rb * A_STRIDE + kb + 16);
        af[ks][4] = *(const uint32_t*)(As + rc * A_STRIDE + kb);
        af[ks][5] = *(const uint32_t*)(As + rd * A_STRIDE + kb);
        af[ks][6] = *(const uint32_t*)(As + rc * A_STRIDE + kb + 16);
        af[ks][7] = *(const uint32_t*)(As + rd * A_STRIDE + kb + 16);
    }

    // ---- per-thread candidate buffers (smem, private slices) ----
    float2* buf = (float2*)(smem + SM_BUF + tid * (4 * CAP_T * 8));
    int   cnt[4] = { 0, 0, 0, 0 };
    float rm[4]  = { -3.4e38f, -3.4e38f, -3.4e38f, -3.4e38f };

#define PUSH(s, v, c) do {                                                     \
        if ((v) >= rm[s] - dl[s]) {                                            \
            rm[s] = fmaxf(rm[s], (v));                                         \
            if (cnt[s] == CAP_T) {                                             \
                float thrC = rm[s] - dl[s];                                    \
                int nc = 0;                                                    \
                _Pragma("unroll")                                              \
                for (int e = 0; e < CAP_T; e++) {                              \
                    float2 t = buf[(s) * CAP_T + e];                           \
                    if (t.x >= thrC) buf[(s) * CAP_T + nc++] = t;              \
                }                                                              \
                cnt[s] = nc;                                                   \
            }                                                                  \
            if (cnt[s] < CAP_T)                                                \
                buf[(s) * CAP_T + cnt[s]++] =                                  \
                    make_float2((v), __int_as_float(c));                       \
            else                                                               \
                OV[rows_[s]] = 1;                                              \
        }                                                                      \
    } while (0)

    // ================= SINGLE PASS: MMA + running-threshold collection ========
#pragma unroll 2
    for (int j = 0; j < 32; ++j) {
        const int colbase = colq + j * 8;
        const int col0 = colbase + (lane & 3) * 2;
        float2 cn = *(const float2*)(CN + col0);
        float a00 = -cn.x, a01 = -cn.y, a02 = -cn.x, a03 = -cn.y;
        float a10 = -cn.x, a11 = -cn.y, a12 = -cn.x, a13 = -cn.y;
        const int bcol = colbase + (lane >> 2);
        const char* brow = smem + SM_B + bcol * 128 + (lane & 3) * 4;
        const int sw = (bcol & 7) << 4;
#pragma unroll
        for (int ks = 0; ks < 4; ks++) {
            uint32_t b0 = *(const uint32_t*)(brow + ((ks * 32)      ^ sw));
            uint32_t b1 = *(const uint32_t*)(brow + ((ks * 32 + 16) ^ sw));
            mma16816(a00, a01, a02, a03, af[ks][0], af[ks][1], af[ks][2], af[ks][3], b0, b1);
            mma16816(a10, a11, a12, a13, af[ks][4], af[ks][5], af[ks][6], af[ks][7], b0, b1);
        }
        PUSH(0, a00, col0); PUSH(0, a01, col0 + 1);
        PUSH(1, a02, col0); PUSH(1, a03, col0 + 1);
        PUSH(2, a10, col0); PUSH(2, a11, col0 + 1);
        PUSH(3, a12, col0); PUSH(3, a13, col0 + 1);
    }
#undef PUSH

    // ---- exact row maxima: quad-combine + publish ----
#pragma unroll
    for (int s = 0; s < 4; s++) {
        rm[s] = fmaxf(rm[s], __shfl_xor_sync(0xffffffffu, rm[s], 1));
        rm[s] = fmaxf(rm[s], __shfl_xor_sync(0xffffffffu, rm[s], 2));
    }
    if ((lane & 3) == 0) {
        atomicMax(&RM[ra], fkey(rm[0]));
        atomicMax(&RM[rb], fkey(rm[1]));
        atomicMax(&RM[rc], fkey(rm[2]));
        atomicMax(&RM[rd], fkey(rm[3]));
    }
    __syncthreads();

    // ---- filter private buffers against final row threshold ----
#pragma unroll
    for (int s = 0; s < 4; s++) {
        float thr = finv(RM[rows_[s]]) - dl[s];
        for (int e = 0; e < cnt[s]; e++) {
            float2 t = buf[s * CAP_T + e];
            if (t.x >= thr) {
                int p = atomicAdd(&CT[rows_[s]], 1);
                if (p < CAND_CAP) CA[rows_[s] * CAND_CAP + p] = t;
            }
        }
    }
    __syncthreads();

    // ---- exact fp32 rescore (1 thread per row, x from gmem) ----
    if (tid < 128) {
        int r = tid;
        int n = CT[r];
        const float4* xr = (const float4*)(inp + (size_t)(row0 + r) * DIMS);
        float bestS = -3.4e38f;
        int   bestI = KCODES;
        if (n <= CAND_CAP && !OV[r]) {
            for (int i = 0; i < n; i++) {
                float2 ce = CA[r * CAND_CAP + i];
                int ix = __float_as_int(ce.y);
                const float4* c4 = (const float4*)(cb + (size_t)ix * DIMS);
                float a0 = 0.f, a1 = 0.f, a2 = 0.f, a3 = 0.f;
#pragma unroll
                for (int q = 0; q < 16; q++) {
                    float4 cv = c4[q];
                    float4 xv = xr[q];
                    a0 = fmaf(xv.x, cv.x, a0);
                    a1 = fmaf(xv.y, cv.y, a1);
                    a2 = fmaf(xv.z, cv.z, a2);
                    a3 = fmaf(xv.w, cv.w, a3);
                }
                float s = (a0 + a1) + (a2 + a3) - CN[ix];
                if (s > bestS || (s == bestS && ix < bestI)) { bestS = s; bestI = ix; }
            }
        } else {
            // overflow fallback (rare): exact full scan
            for (int ix = 0; ix < KCODES; ix++) {
                const float4* c4 = (const float4*)(cb + (size_t)ix * DIMS);
                float a0 = 0.f, a1 = 0.f, a2 = 0.f, a3 = 0.f;
#pragma unroll
                for (int q = 0; q < 16; q++) {
                    float4 cv = c4[q];
                    float4 xv = xr[q];
                    a0 = fmaf(xv.x, cv.x, a0);
                    a1 = fmaf(xv.y, cv.y, a1);
                    a2 = fmaf(xv.z, cv.z, a2);
                    a3 = fmaf(xv.w, cv.w, a3);
                }
                float s = (a0 + a1) + (a2 + a3) - CN[ix];
                if (s > bestS) { bestS = s; bestI = ix; }
            }
        }
        TK[r] = bestI;
        out[QOUT + row0 + r] = (float)bestI;
        atomicAdd(&g_counts[bestI], 1u);
    }
    __syncthreads();

    // ---- quantized + straight-through + losses (cooperative, coalesced) ----
    float esum = 0.0f, qsum = 0.0f;
#pragma unroll
    for (int i = 0; i < 4; i++) {
        int idx = tid + i * THREADS;
        int r = idx >> 4, q = idx & 15;
        int ix = TK[r];
        float4 cv = *(const float4*)(cb + (size_t)ix * DIMS + q * 4);
        float4 xv = *(const float4*)(inp + (size_t)(row0 + r) * DIMS + q * 4);
        float d0v = cv.x - xv.x, d1v = cv.y - xv.y, d2v = cv.z - xv.z, d3v = cv.w - xv.w;
        float q0 = xv.x + d0v, q1 = xv.y + d1v, q2 = xv.z + d2v, q3 = xv.w + d3v;
        float e0 = q0 - xv.x, e1 = q1 - xv.y, e2 = q2 - xv.z, e3 = q3 - xv.w;
        esum += e0 * e0 + e1 * e1 + e2 * e2 + e3 * e3;
        qsum += d0v * d0v + d1v * d1v + d2v * d2v + d3v * d3v;
        *(float4*)(out + (size_t)(row0 + r) * DIMS + q * 4) = make_float4(q0, q1, q2, q3);
    }
#pragma unroll
    for (int off = 16; off > 0; off >>= 1) {
        esum += __shfl_xor_sync(0xffffffffu, esum, off);
        qsum += __shfl_xor_sync(0xffffffffu, qsum, off);
    }
    if (lane == 0) {
        atomicAdd(&g_loss[0], esum);
        atomicAdd(&g_loss[1], qsum);
    }

    // ---- last-CTA finalize ----
    if (tid == 0) {
        __threadfence();
        *FLAG = (atomicAdd(&g_done, 1u) == GRID - 1) ? 1 : 0;
    }
    __syncthreads();
    if (*FLAG) {
        volatile unsigned* vc = g_counts;
        float part = 0.0f;
#pragma unroll
        for (int i = 0; i < 2; i++) {
            float p = (float)vc[tid + i * THREADS] / (float)N_ROWS;
            part += -p * logf(p + 1e-10f);
        }
#pragma unroll
        for (int off = 16; off > 0; off >>= 1)
            part += __shfl_xor_sync(0xffffffffu, part, off);
        float* red = (float*)RM;
        if (lane == 0) red[w] = part;
        __syncthreads();
        if (tid == 0) {
            float H = 0.0f;
#pragma unroll
            for (int i = 0; i < 16; i++) H += red[i];
            volatile float* vl = g_loss;
            float inv = 1.0f / (float)((long long)N_ROWS * DIMS);
            float e_mean = vl[0] * inv;
            float q_mean = vl[1] * inv;
            float commit = 0.25f * e_mean;
            out[QOUT + N_ROWS + 0] = commit + q_mean;
            out[QOUT + N_ROWS + 1] = commit;
            out[QOUT + N_ROWS + 2] = q_mean;
            out[QOUT + N_ROWS + 3] = expf(H);
        }
    }
}

extern "C" void kernel_launch(void* const* d_in, const int* in_sizes, int n_in,
                              void* d_out, int out_size)
{
    const float* inp = (const float*)d_in[0];
    const float* cb  = (const float*)d_in[1];
    float* out = (float*)d_out;

    cudaFuncSetAttribute(vq_main, cudaFuncAttributeMaxDynamicSharedMemorySize, SMEM_TOTAL);

    vq_prep<<<1, 1024>>>(cb);
    vq_main<<<GRID, THREADS, SMEM_TOTAL>>>(inp, cb, out);
}

// round 9
// speedup vs baseline: 16.1451x; 16.1451x over previous
#include <cuda_runtime.h>
#include <cuda_bf16.h>
#include <cstdint>

// ---------------- problem constants ----------------
#define N_ROWS   262144
#define DIMS     64
#define KCODES   1024
#define BM       128
#define THREADS  512
#define GRID     (N_ROWS / BM)              // 2048
#define QOUT     (N_ROWS * DIMS)
#define CAND_CAP 8

// ---------------- smem layout (bytes) ----------------
#define SM_X     0                          // 128 x 272B fp32 rows (padded)
#define SM_A     34816                      // 128 x 144B bf16 rows (padded)
#define SM_B     53248                      // 1024 x 144B bf16 rows (padded)
#define SM_CN    200704                     // 1024 fp32
#define SM_RMAX  204800                     // 128 u32 keys (reused as reduce buf)
#define SM_CNT   205312                     // 128 int
#define SM_CAND  205824                     // 128 x 8 x 8B
#define SM_TOK   214016                     // 128 int
#define SM_DELTA 214528                     // 128 fp32
#define SM_FLAG  215040                     // 4B last-CTA flag
#define SMEM_TOTAL 215056

#define A_STRIDE 144
#define B_STRIDE 144
#define X_STRIDE 272

// ---------------- device globals ----------------
__device__ __align__(16) float    g_cnorm[KCODES];
__device__ __align__(16) uint32_t g_cbbf16[KCODES * DIMS / 2];
__device__ unsigned int           g_counts[KCODES];
__device__ float                  g_loss[2];
__device__ int                    g_cmax_bits;
__device__ unsigned int           g_done;

// ---------------- helpers ----------------
static __device__ __forceinline__ unsigned fkey(float f) {
    int b = __float_as_int(f);
    return (unsigned)(b >= 0 ? (b | 0x80000000) : ~b);
}
static __device__ __forceinline__ float finv(unsigned k) {
    int b = (k & 0x80000000u) ? (int)(k & 0x7fffffffu) : ~(int)k;
    return __int_as_float(b);
}
static __device__ __forceinline__ void mma16816(
    float& c0, float& c1, float& c2, float& c3,
    uint32_t a0, uint32_t a1, uint32_t a2, uint32_t a3,
    uint32_t b0, uint32_t b1)
{
    asm volatile(
        "mma.sync.aligned.m16n8k16.row.col.f32.bf16.bf16.f32 "
        "{%0,%1,%2,%3}, {%4,%5,%6,%7}, {%8,%9}, {%0,%1,%2,%3};"
        : "+f"(c0), "+f"(c1), "+f"(c2), "+f"(c3)
        : "r"(a0), "r"(a1), "r"(a2), "r"(a3), "r"(b0), "r"(b1));
}

// ---------------- prep: resets + cnorm + cmax + bf16 codebook ----------------
__global__ void vq_prep(const float* __restrict__ cb) {
    int k = threadIdx.x;   // 1024 threads, 1 block
    g_counts[k] = 0u;
    if (k < 2) g_loss[k] = 0.0f;
    if (k == 2) g_done = 0u;

    const float4* c4 = (const float4*)(cb + (size_t)k * DIMS);
    uint32_t* ob = g_cbbf16 + k * (DIMS / 2);
    float s = 0.0f;
#pragma unroll
    for (int j = 0; j < 16; j++) {
        float4 v = c4[j];
        s += v.x * v.x + v.y * v.y + v.z * v.z + v.w * v.w;
        __nv_bfloat162 p0 = __float22bfloat162_rn(make_float2(v.x, v.y));
        __nv_bfloat162 p1 = __float22bfloat162_rn(make_float2(v.z, v.w));
        ob[j * 2 + 0] = *(uint32_t*)&p0;
        ob[j * 2 + 1] = *(uint32_t*)&p1;
    }
    g_cnorm[k] = 0.5f * s;
    atomicMax(&g_cmax_bits, __float_as_int(sqrtf(s)));
}

// ---------------- main ----------------
extern __shared__ char smem[];

__global__ __launch_bounds__(THREADS, 1)
void vq_main(const float* __restrict__ inp, const float* __restrict__ cb,
             float* __restrict__ out)
{
    const int tid  = threadIdx.x;
    const int w    = tid >> 5;
    const int lane = tid & 31;
    const int row0 = blockIdx.x * BM;

    float*    Xs = (float*)(smem + SM_X);
    char*     As = smem + SM_A;
    char*     Bs = smem + SM_B;
    float*    CN = (float*)(smem + SM_CN);
    unsigned* RM = (unsigned*)(smem + SM_RMAX);
    int*      CT = (int*)(smem + SM_CNT);
    float2*   CA = (float2*)(smem + SM_CAND);
    int*      TK = (int*)(smem + SM_TOK);
    float*    DL = (float*)(smem + SM_DELTA);
    int*      FLAG = (int*)(smem + SM_FLAG);

    // ---- fills ----
    if (tid < 128) { RM[tid] = 0u; CT[tid] = 0; }
#pragma unroll
    for (int i = 0; i < 4; i++) {           // X fp32 + A bf16
        int idx = tid + i * THREADS;
        int r = idx >> 4, j = idx & 15;
        float4 v = *(const float4*)(inp + (size_t)(row0 + r) * DIMS + j * 4);
        *(float4*)(Xs + r * (X_STRIDE / 4) + j * 4) = v;
        __nv_bfloat162 p0 = __float22bfloat162_rn(make_float2(v.x, v.y));
        __nv_bfloat162 p1 = __float22bfloat162_rn(make_float2(v.z, v.w));
        *(uint2*)(As + r * A_STRIDE + j * 8) = make_uint2(*(uint32_t*)&p0, *(uint32_t*)&p1);
    }
#pragma unroll
    for (int i = 0; i < 16; i++) {          // B bf16
        int idx = tid + i * THREADS;
        int c = idx >> 3, j = idx & 7;
        uint4 v = *(const uint4*)(g_cbbf16 + (size_t)idx * 4);
        *(uint4*)(Bs + c * B_STRIDE + j * 16) = v;
    }
#pragma unroll
    for (int i = 0; i < 2; i++) {           // cnorm
        int idx = tid + i * THREADS;
        CN[idx] = g_cnorm[idx];
    }
    __syncthreads();

    // ---- per-row certified margin delta ----
    if (tid < 128) {
        const float4* xr = (const float4*)(Xs + tid * (X_STRIDE / 4));
        float s = 0.0f;
#pragma unroll
        for (int j = 0; j < 16; j++) {
            float4 v = xr[j];
            s += v.x * v.x + v.y * v.y + v.z * v.z + v.w * v.w;
        }
        DL[tid] = sqrtf(s) * __int_as_float(g_cmax_bits) * (2.2f / 256.0f) + 1e-4f;
    }
    __syncthreads();

    // ---- warp work assignment: 32 rows x 256 codes ----
    const int rowblk = (w & 3) * 32;
    const int colq   = (w >> 2) * 256;
    const int ra = rowblk + (lane >> 2);
    const int rb = ra + 8;
    const int rc = ra + 16;
    const int rd = ra + 24;

    // ---- A fragments: persistent registers (4 ks x {blk0:4, blk1:4}) ----
    uint32_t af[4][8];
#pragma unroll
    for (int ks = 0; ks < 4; ks++) {
        int kb = ks * 32 + (lane & 3) * 4;
        af[ks][0] = *(const uint32_t*)(As + ra * A_STRIDE + kb);
        af[ks][1] = *(const uint32_t*)(As + rb * A_STRIDE + kb);
        af[ks][2] = *(const uint32_t*)(As + ra * A_STRIDE + kb + 16);
        af[ks][3] = *(const uint32_t*)(As + rb * A_STRIDE + kb + 16);
        af[ks][4] = *(const uint32_t*)(As + rc * A_STRIDE + kb);
        af[ks][5] = *(const uint32_t*)(As + rd * A_STRIDE + kb);
        af[ks][6] = *(const uint32_t*)(As + rc * A_STRIDE + kb + 16);
        af[ks][7] = *(const uint32_t*)(As + rd * A_STRIDE + kb + 16);
    }

    // ================= PASS 1: exact approx-max per row =================
    // 2-j interleave: 4 independent MMA chains in flight per iteration.
    float gma[8], gmb[8], gmc[8], gmd[8];
#pragma unroll
    for (int g = 0; g < 8; g++) {
        gma[g] = -3.4e38f; gmb[g] = -3.4e38f;
        gmc[g] = -3.4e38f; gmd[g] = -3.4e38f;
    }

#pragma unroll 2
    for (int j = 0; j < 32; j += 2) {
        int col0A = colq + j * 8 + (lane & 3) * 2;
        float2 cnA = *(const float2*)(CN + col0A);
        float2 cnB = *(const float2*)(CN + col0A + 8);
        float p0[4] = { -cnA.x, -cnA.y, -cnA.x, -cnA.y };   // j,   rows blk0
        float p1[4] = { -cnA.x, -cnA.y, -cnA.x, -cnA.y };   // j,   rows blk1
        float q0[4] = { -cnB.x, -cnB.y, -cnB.x, -cnB.y };   // j+1, rows blk0
        float q1[4] = { -cnB.x, -cnB.y, -cnB.x, -cnB.y };   // j+1, rows blk1
        const char* bpA = Bs + (colq + j * 8 + (lane >> 2)) * B_STRIDE + (lane & 3) * 4;
        const char* bpB = bpA + 8 * B_STRIDE;
#pragma unroll
        for (int ks = 0; ks < 4; ks++) {
            uint32_t bA0 = *(const uint32_t*)(bpA + ks * 32);
            uint32_t bA1 = *(const uint32_t*)(bpA + ks * 32 + 16);
            uint32_t bB0 = *(const uint32_t*)(bpB + ks * 32);
            uint32_t bB1 = *(const uint32_t*)(bpB + ks * 32 + 16);
            mma16816(p0[0], p0[1], p0[2], p0[3],
                     af[ks][0], af[ks][1], af[ks][2], af[ks][3], bA0, bA1);
            mma16816(q0[0], q0[1], q0[2], q0[3],
                     af[ks][0], af[ks][1], af[ks][2], af[ks][3], bB0, bB1);
            mma16816(p1[0], p1[1], p1[2], p1[3],
                     af[ks][4], af[ks][5], af[ks][6], af[ks][7], bA0, bA1);
            mma16816(q1[0], q1[1], q1[2], q1[3],
                     af[ks][4], af[ks][5], af[ks][6], af[ks][7], bB0, bB1);
        }
        int g = j >> 2;
        gma[g] = fmaxf(gma[g], fmaxf(fmaxf(p0[0], p0[1]), fmaxf(q0[0], q0[1])));
        gmb[g] = fmaxf(gmb[g], fmaxf(fmaxf(p0[2], p0[3]), fmaxf(q0[2], q0[3])));
        gmc[g] = fmaxf(gmc[g], fmaxf(fmaxf(p1[0], p1[1]), fmaxf(q1[0], q1[1])));
        gmd[g] = fmaxf(gmd[g], fmaxf(fmaxf(p1[2], p1[3]), fmaxf(q1[2], q1[3])));
    }

    // quad-combine (lanes of a quad share the same rows)
    float rma = -3.4e38f, rmb = -3.4e38f, rmc = -3.4e38f, rmd = -3.4e38f;
#pragma unroll
    for (int g = 0; g < 8; g++) {
        gma[g] = fmaxf(gma[g], __shfl_xor_sync(0xffffffffu, gma[g], 1));
        gma[g] = fmaxf(gma[g], __shfl_xor_sync(0xffffffffu, gma[g], 2));
        gmb[g] = fmaxf(gmb[g], __shfl_xor_sync(0xffffffffu, gmb[g], 1));
        gmb[g] = fmaxf(gmb[g], __shfl_xor_sync(0xffffffffu, gmb[g], 2));
        gmc[g] = fmaxf(gmc[g], __shfl_xor_sync(0xffffffffu, gmc[g], 1));
        gmc[g] = fmaxf(gmc[g], __shfl_xor_sync(0xffffffffu, gmc[g], 2));
        gmd[g] = fmaxf(gmd[g], __shfl_xor_sync(0xffffffffu, gmd[g], 1));
        gmd[g] = fmaxf(gmd[g], __shfl_xor_sync(0xffffffffu, gmd[g], 2));
        rma = fmaxf(rma, gma[g]); rmb = fmaxf(rmb, gmb[g]);
        rmc = fmaxf(rmc, gmc[g]); rmd = fmaxf(rmd, gmd[g]);
    }
    if ((lane & 3) == 0) {
        atomicMax(&RM[ra], fkey(rma));
        atomicMax(&RM[rb], fkey(rmb));
        atomicMax(&RM[rc], fkey(rmc));
        atomicMax(&RM[rd], fkey(rmd));
    }
    __syncthreads();

    // ================= PASS 2: fixed-threshold candidate collection =================
    const float thra = finv(RM[ra]) - DL[ra];
    const float thrb = finv(RM[rb]) - DL[rb];
    const float thrc = finv(RM[rc]) - DL[rc];
    const float thrd = finv(RM[rd]) - DL[rd];

#define PUSH2(val, row, thr, col) do {                                      \
        if ((val) >= (thr)) {                                               \
            int p = atomicAdd(&CT[row], 1);                                 \
            if (p < CAND_CAP)                                               \
                CA[(row) * CAND_CAP + p] =                                  \
                    make_float2((val), __int_as_float(col));                \
        }                                                                   \
    } while (0)

    for (int g = 0; g < 8; g++) {
        bool need = (gma[g] >= thra) || (gmb[g] >= thrb) ||
                    (gmc[g] >= thrc) || (gmd[g] >= thrd);
        if (!__any_sync(0xffffffffu, need)) continue;
#pragma unroll
        for (int jj = 0; jj < 4; jj += 2) {
            int j = g * 4 + jj;
            int col0A = colq + j * 8 + (lane & 3) * 2;
            int col0B = col0A + 8;
            float2 cnA = *(const float2*)(CN + col0A);
            float2 cnB = *(const float2*)(CN + col0B);
            float p0[4] = { -cnA.x, -cnA.y, -cnA.x, -cnA.y };
            float p1[4] = { -cnA.x, -cnA.y, -cnA.x, -cnA.y };
            float q0[4] = { -cnB.x, -cnB.y, -cnB.x, -cnB.y };
            float q1[4] = { -cnB.x, -cnB.y, -cnB.x, -cnB.y };
            const char* bpA = Bs + (colq + j * 8 + (lane >> 2)) * B_STRIDE + (lane & 3) * 4;
            const char* bpB = bpA + 8 * B_STRIDE;
#pragma unroll
            for (int ks = 0; ks < 4; ks++) {
                uint32_t bA0 = *(const uint32_t*)(bpA + ks * 32);
                uint32_t bA1 = *(const uint32_t*)(bpA + ks * 32 + 16);
                uint32_t bB0 = *(const uint32_t*)(bpB + ks * 32);
                uint32_t bB1 = *(const uint32_t*)(bpB + ks * 32 + 16);
                mma16816(p0[0], p0[1], p0[2], p0[3],
                         af[ks][0], af[ks][1], af[ks][2], af[ks][3], bA0, bA1);
                mma16816(q0[0], q0[1], q0[2], q0[3],
                         af[ks][0], af[ks][1], af[ks][2], af[ks][3], bB0, bB1);
                mma16816(p1[0], p1[1], p1[2], p1[3],
                         af[ks][4], af[ks][5], af[ks][6], af[ks][7], bA0, bA1);
                mma16816(q1[0], q1[1], q1[2], q1[3],
                         af[ks][4], af[ks][5], af[ks][6], af[ks][7], bB0, bB1);
            }
            PUSH2(p0[0], ra, thra, col0A); PUSH2(p0[1], ra, thra, col0A + 1);
            PUSH2(p0[2], rb, thrb, col0A); PUSH2(p0[3], rb, thrb, col0A + 1);
            PUSH2(p1[0], rc, thrc, col0A); PUSH2(p1[1], rc, thrc, col0A + 1);
            PUSH2(p1[2], rd, thrd, col0A); PUSH2(p1[3], rd, thrd, col0A + 1);
            PUSH2(q0[0], ra, thra, col0B); PUSH2(q0[1], ra, thra, col0B + 1);
            PUSH2(q0[2], rb, thrb, col0B); PUSH2(q0[3], rb, thrb, col0B + 1);
            PUSH2(q1[0], rc, thrc, col0B); PUSH2(q1[1], rc, thrc, col0B + 1);
            PUSH2(q1[2], rd, thrd, col0B); PUSH2(q1[3], rd, thrd, col0B + 1);
        }
    }
#undef PUSH2
    __syncthreads();

    // ---- exact fp32 rescore (1 thread per row) ----
    if (tid < 128) {
        int r = tid;
        int n = CT[r];
        const float* xrow = Xs + r * (X_STRIDE / 4);
        float bestS = -3.4e38f;
        int   bestI = KCODES;
        if (n <= CAND_CAP) {
            for (int i = 0; i < n; i++) {
                float2 ce = CA[r * CAND_CAP + i];
                int ix = __float_as_int(ce.y);
                const float4* c4 = (const float4*)(cb + (size_t)ix * DIMS);
                float a0 = 0.f, a1 = 0.f, a2 = 0.f, a3 = 0.f;
#pragma unroll
                for (int q = 0; q < 16; q++) {
                    float4 cv = c4[q];
                    float4 xv = *(const float4*)(xrow + q * 4);
                    a0 = fmaf(xv.x, cv.x, a0);
                    a1 = fmaf(xv.y, cv.y, a1);
                    a2 = fmaf(xv.z, cv.z, a2);
                    a3 = fmaf(xv.w, cv.w, a3);
                }
                float s = (a0 + a1) + (a2 + a3) - CN[ix];
                if (s > bestS || (s == bestS && ix < bestI)) { bestS = s; bestI = ix; }
            }
        } else {
            // overflow fallback (astronomically rare): exact full scan
            for (int ix = 0; ix < KCODES; ix++) {
                const float4* c4 = (const float4*)(cb + (size_t)ix * DIMS);
                float a0 = 0.f, a1 = 0.f, a2 = 0.f, a3 = 0.f;
#pragma unroll
                for (int q = 0; q < 16; q++) {
                    float4 cv = c4[q];
                    float4 xv = *(const float4*)(xrow + q * 4);
                    a0 = fmaf(xv.x, cv.x, a0);
                    a1 = fmaf(xv.y, cv.y, a1);
                    a2 = fmaf(xv.z, cv.z, a2);
                    a3 = fmaf(xv.w, cv.w, a3);
                }
                float s = (a0 + a1) + (a2 + a3) - CN[ix];
                if (s > bestS) { bestS = s; bestI = ix; }
            }
        }
        TK[r] = bestI;
        out[QOUT + row0 + r] = (float)bestI;
        atomicAdd(&g_counts[bestI], 1u);
    }
    __syncthreads();

    // ---- quantized + straight-through + losses (cooperative, coalesced) ----
    float esum = 0.0f, qsum = 0.0f;
#pragma unroll
    for (int i = 0; i < 4; i++) {
        int idx = tid + i * THREADS;
        int r = idx >> 4, q = idx & 15;
        int ix = TK[r];
        float4 cv = *(const float4*)(cb + (size_t)ix * DIMS + q * 4);
        float4 xv = *(const float4*)(Xs + r * (X_STRIDE / 4) + q * 4);
        float d0v = cv.x - xv.x, d1v = cv.y - xv.y, d2v = cv.z - xv.z, d3v = cv.w - xv.w;
        float q0 = xv.x + d0v, q1 = xv.y + d1v, q2 = xv.z + d2v, q3 = xv.w + d3v;
        float e0 = q0 - xv.x, e1 = q1 - xv.y, e2 = q2 - xv.z, e3 = q3 - xv.w;
        esum += e0 * e0 + e1 * e1 + e2 * e2 + e3 * e3;
        qsum += d0v * d0v + d1v * d1v + d2v * d2v + d3v * d3v;
        *(float4*)(out + (size_t)(row0 + r) * DIMS + q * 4) = make_float4(q0, q1, q2, q3);
    }
#pragma unroll
    for (int off = 16; off > 0; off >>= 1) {
        esum += __shfl_xor_sync(0xffffffffu, esum, off);
        qsum += __shfl_xor_sync(0xffffffffu, qsum, off);
    }
    if (lane == 0) {
        atomicAdd(&g_loss[0], esum);
        atomicAdd(&g_loss[1], qsum);
    }

    // ---- last-CTA finalize (perplexity + scalar losses) ----
    if (tid == 0) {
        __threadfence();
        *FLAG = (atomicAdd(&g_done, 1u) == GRID - 1) ? 1 : 0;
    }
    __syncthreads();
    if (*FLAG) {
        volatile unsigned* vc = g_counts;
        float part = 0.0f;
#pragma unroll
        for (int i = 0; i < 2; i++) {
            float p = (float)vc[tid + i * THREADS] / (float)N_ROWS;
            part += -p * logf(p + 1e-10f);
        }
#pragma unroll
        for (int off = 16; off > 0; off >>= 1)
            part += __shfl_xor_sync(0xffffffffu, part, off);
        float* red = (float*)RM;            // reuse: 16 warp partials
        if (lane == 0) red[w] = part;
        __syncthreads();
        if (tid == 0) {
            float H = 0.0f;
#pragma unroll
            for (int i = 0; i < 16; i++) H += red[i];
            volatile float* vl = g_loss;
            float inv = 1.0f / (float)((long long)N_ROWS * DIMS);
            float e_mean = vl[0] * inv;
            float q_mean = vl[1] * inv;
            float commit = 0.25f * e_mean;
            out[QOUT + N_ROWS + 0] = commit + q_mean;
            out[QOUT + N_ROWS + 1] = commit;
            out[QOUT + N_ROWS + 2] = q_mean;
            out[QOUT + N_ROWS + 3] = expf(H);
        }
    }
}

extern "C" void kernel_launch(void* const* d_in, const int* in_sizes, int n_in,
                              void* d_out, int out_size)
{
    const float* inp = (const float*)d_in[0];
    const float* cb  = (const float*)d_in[1];
    float* out = (float*)d_out;

    cudaFuncSetAttribute(vq_main, cudaFuncAttributeMaxDynamicSharedMemorySize, SMEM_TOTAL);

    vq_prep<<<1, 1024>>>(cb);
    vq_main<<<GRID, THREADS, SMEM_TOTAL>>>(inp, cb, out);
}